// round 2
// baseline (speedup 1.0000x reference)
#include <cuda_runtime.h>

#define NPOS   65536
#define HW_    4096
#define KCB    4
#define SENT   1024
#define DIM    64
#define TILE_N 128
#define TILE_S 128
#define ZQ_ELEMS 16777216
#define MARGIN 4e-5f

// smem float offsets
#define LDA 129
#define LDB 68
#define AL_OFF 0                    // As_lin  [64][129]  exact z tile
#define AP_OFF 8256                 // As_perm [8 mt][8 kc][32 lane][4] tf32
#define BL_OFF 16448                // Bs_lin  [128][68]  exact codebook chunk
#define BP_OFF 25152                // Bs_perm [16 nt][8 kc][32 lane][2] tf32
#define ZN_OFF 33344                // zn[128] exact
#define EN_OFF 33472                // en[128] exact
#define SMEM_FLOATS 33600

__device__ float  g_enorm[KCB * SENT];
__device__ int    g_idx[KCB * NPOS];
__device__ double g_part[KCB * (NPOS / 256)];

__device__ __forceinline__ unsigned f2tf32(float x) {
    unsigned r; asm("cvt.rna.tf32.f32 %0, %1;" : "=r"(r) : "f"(x)); return r;
}
__device__ __forceinline__ void mma_tf32(float c[4], const unsigned a[4], const unsigned b[2]) {
    asm volatile("mma.sync.aligned.m16n8k8.row.col.f32.tf32.tf32.f32 "
                 "{%0,%1,%2,%3}, {%4,%5,%6,%7}, {%8,%9}, {%0,%1,%2,%3};"
                 : "+f"(c[0]), "+f"(c[1]), "+f"(c[2]), "+f"(c[3])
                 : "r"(a[0]), "r"(a[1]), "r"(a[2]), "r"(a[3]), "r"(b[0]), "r"(b[1]));
}

// ---------------------------------------------------------------------------
__global__ void enorm_kernel(const float* __restrict__ cb) {
    int j = blockIdx.x * 256 + threadIdx.x;
    const float* e = cb + (size_t)j * DIM;
    float s = 0.f;
#pragma unroll
    for (int d = 0; d < DIM; d++) {
        float v = e[d];
        s = __fadd_rn(s, __fmul_rn(v, v));
    }
    g_enorm[j] = s;
}

// ---------------------------------------------------------------------------
// TF32 tensor-core distance GEMM + margin-gated exact-fp32 rescore + argmin.
// Block 256 thr (8 warps, 2x4), 128 positions x 1024 entries (8 chunks of 128).
// ---------------------------------------------------------------------------
__global__ void __launch_bounds__(256, 1)
argmin_tc_kernel(const float* __restrict__ z, const float* __restrict__ cb,
                 float* __restrict__ out, int idx_off) {
    extern __shared__ float sm[];
    const int k        = blockIdx.y;
    const int tileBase = blockIdx.x * TILE_N;
    const int b        = tileBase >> 12;
    const int hw0      = tileBase & (HW_ - 1);
    const int tid      = threadIdx.x;
    const int warp     = tid >> 5;
    const int lane     = tid & 31;
    const int g        = lane >> 2;     // groupID
    const int tg       = lane & 3;      // threadID in group
    const int wm       = warp >> 2;     // warp row group (0..1): rows 64*wm..
    const int wn       = warp & 3;      // warp col group (0..3): cols 32*wn..

    // ---- load exact z tile (coalesced) ----
    const float* zbase = z + ((size_t)(b * 256 + k * DIM)) * HW_ + hw0;
    for (int i0 = tid; i0 < DIM * TILE_N; i0 += 256) {
        int d = i0 >> 7, i = i0 & 127;
        sm[AL_OFF + d * LDA + i] = zbase[(size_t)d * HW_ + i];
    }
    __syncthreads();

    // ---- exact znorm (reference rounding: square, then sequential fp32 sum) ----
    if (tid < TILE_N) {
        float s = 0.f;
        for (int d = 0; d < DIM; d++) {
            float v = sm[AL_OFF + d * LDA + tid];
            s = __fadd_rn(s, __fmul_rn(v, v));
        }
        sm[ZN_OFF + tid] = s;
    }

    // ---- build tf32 A fragments (once): slot (mt,kc,lane) -> float4 ----
    for (int s0 = tid; s0 < 8 * 8 * 32; s0 += 256) {
        int ln = s0 & 31, kc = (s0 >> 5) & 7, mt = s0 >> 8;
        int gg = ln >> 2, tt = ln & 3;
        int r0 = 16 * mt + gg, c0 = 8 * kc + tt;
        uint4 v;
        v.x = f2tf32(sm[AL_OFF + c0 * LDA + r0]);
        v.y = f2tf32(sm[AL_OFF + c0 * LDA + r0 + 8]);
        v.z = f2tf32(sm[AL_OFF + (c0 + 4) * LDA + r0]);
        v.w = f2tf32(sm[AL_OFF + (c0 + 4) * LDA + r0 + 8]);
        *(uint4*)&sm[AP_OFF + (size_t)s0 * 4] = v;
    }

    float bestApprox[8], bestD[8];
    int   bestI[8];
#pragma unroll
    for (int u = 0; u < 8; u++) {
        bestApprox[u] = __int_as_float(0x7f800000);
        bestD[u]      = __int_as_float(0x7f800000);
        bestI[u]      = 0;
    }

    const float* cbk = cb + (size_t)k * SENT * DIM;
    for (int chunk = 0; chunk < SENT / TILE_S; chunk++) {
        __syncthreads();
        // ---- load exact codebook chunk (float4 coalesced) + exact enorm ----
        const float4* cbc4 = (const float4*)(cbk + (size_t)chunk * TILE_S * DIM);
        for (int t = tid; t < TILE_S * DIM / 4; t += 256) {
            int j = t >> 4, c4 = t & 15;
            *(float4*)&sm[BL_OFF + j * LDB + 4 * c4] = cbc4[t];
        }
        if (tid < TILE_S) sm[EN_OFF + tid] = g_enorm[k * SENT + chunk * TILE_S + tid];
        __syncthreads();

        // ---- build tf32 B fragments: slot (nt,kc,lane) -> float2 ----
        for (int s0 = tid; s0 < 16 * 8 * 32; s0 += 256) {
            int ln = s0 & 31, kc = (s0 >> 5) & 7, nt = s0 >> 8;
            int gg = ln >> 2, tt = ln & 3;
            int j = 8 * nt + gg, c0 = 8 * kc + tt;
            uint2 v;
            v.x = f2tf32(sm[BL_OFF + j * LDB + c0]);
            v.y = f2tf32(sm[BL_OFF + j * LDB + c0 + 4]);
            *(uint2*)&sm[BP_OFF + (size_t)s0 * 2] = v;
        }
        __syncthreads();

        // ---- tensor-core GEMM: warp computes 64x32 of the 128x128 chunk ----
        float acc[4][4][4];
#pragma unroll
        for (int mt = 0; mt < 4; mt++)
#pragma unroll
            for (int nt = 0; nt < 4; nt++)
#pragma unroll
                for (int c = 0; c < 4; c++) acc[mt][nt][c] = 0.f;

#pragma unroll
        for (int kc = 0; kc < 8; kc++) {
            uint4 af[4]; uint2 bf[4];
#pragma unroll
            for (int mt = 0; mt < 4; mt++)
                af[mt] = *(const uint4*)&sm[AP_OFF + ((((4 * wm + mt) * 8 + kc) * 32 + lane)) * 4];
#pragma unroll
            for (int nt = 0; nt < 4; nt++)
                bf[nt] = *(const uint2*)&sm[BP_OFF + ((((4 * wn + nt) * 8 + kc) * 32 + lane)) * 2];
#pragma unroll
            for (int mt = 0; mt < 4; mt++)
#pragma unroll
                for (int nt = 0; nt < 4; nt++)
                    mma_tf32(acc[mt][nt], (const unsigned*)&af[mt], (const unsigned*)&bf[nt]);
        }

        // ---- epilogue: approx dist (overwrite acc), per-row running min ----
#pragma unroll
        for (int mt = 0; mt < 4; mt++) {
            int r0 = 64 * wm + 16 * mt + g;
            float z0 = sm[ZN_OFF + r0], z1 = sm[ZN_OFF + r0 + 8];
#pragma unroll
            for (int nt = 0; nt < 4; nt++) {
                int cl = 32 * wn + 8 * nt + 2 * tg;
                float e0 = sm[EN_OFF + cl], e1 = sm[EN_OFF + cl + 1];
                acc[mt][nt][0] = z0 + e0 - 2.f * acc[mt][nt][0];
                acc[mt][nt][1] = z0 + e1 - 2.f * acc[mt][nt][1];
                acc[mt][nt][2] = z1 + e0 - 2.f * acc[mt][nt][2];
                acc[mt][nt][3] = z1 + e1 - 2.f * acc[mt][nt][3];
            }
        }
#pragma unroll
        for (int mt = 0; mt < 4; mt++)
#pragma unroll
            for (int h = 0; h < 2; h++) {
                int slot = mt * 2 + h;
                float m = acc[mt][0][2 * h];
#pragma unroll
                for (int nt = 0; nt < 4; nt++) {
                    m = fminf(m, acc[mt][nt][2 * h]);
                    m = fminf(m, acc[mt][nt][2 * h + 1]);
                }
                m = fminf(m, __shfl_xor_sync(0xffffffff, m, 1));
                m = fminf(m, __shfl_xor_sync(0xffffffff, m, 2));
                bestApprox[slot] = fminf(bestApprox[slot], m);
            }

        // ---- margin-gated exact rescore (guarantees exact argmin) ----
#pragma unroll
        for (int mt = 0; mt < 4; mt++)
#pragma unroll
            for (int nt = 0; nt < 4; nt++)
#pragma unroll
                for (int cc = 0; cc < 4; cc++) {
                    int h = cc >> 1, slot = mt * 2 + h;
                    if (acc[mt][nt][cc] < bestApprox[slot] + MARGIN) {
                        int row  = 64 * wm + 16 * mt + g + 8 * h;
                        int jloc = 32 * wn + 8 * nt + 2 * tg + (cc & 1);
                        float dot = 0.f;
#pragma unroll 8
                        for (int d = 0; d < DIM; d++)
                            dot = __fmaf_rn(sm[AL_OFF + d * LDA + row],
                                            sm[BL_OFF + jloc * LDB + d], dot);
                        float de = __fsub_rn(__fadd_rn(sm[ZN_OFF + row], sm[EN_OFF + jloc]),
                                             __fmul_rn(2.0f, dot));
                        int jg = chunk * TILE_S + jloc;
                        if (de < bestD[slot] || (de == bestD[slot] && jg < bestI[slot])) {
                            bestD[slot] = de;
                            bestI[slot] = jg;
                        }
                    }
                }
    }
    __syncthreads();

    // ---- cross-thread lexicographic reduce: 16 partials per row ----
    float* rd = &sm[AP_OFF];
    int*   ri = (int*)&sm[AP_OFF + TILE_N * 16];
    int colIdx = wn * 4 + tg;
#pragma unroll
    for (int mt = 0; mt < 4; mt++)
#pragma unroll
        for (int h = 0; h < 2; h++) {
            int row = 64 * wm + 16 * mt + g + 8 * h;
            rd[row * 16 + colIdx] = bestD[mt * 2 + h];
            ri[row * 16 + colIdx] = bestI[mt * 2 + h];
        }
    __syncthreads();
    if (tid < TILE_N) {
        float bd = rd[tid * 16];
        int   bi = ri[tid * 16];
#pragma unroll
        for (int t = 1; t < 16; t++) {
            float dd = rd[tid * 16 + t];
            int   ii = ri[tid * 16 + t];
            if (dd < bd || (dd == bd && ii < bi)) { bd = dd; bi = ii; }
        }
        int n = tileBase + tid;
        g_idx[k * NPOS + n] = bi;
        if (idx_off >= 0) out[(size_t)idx_off + k * NPOS + n] = (float)bi;
    }
}

// ---------------------------------------------------------------------------
__global__ void scatter_kernel(const float* __restrict__ z, const float* __restrict__ cb,
                               float* __restrict__ out) {
    const int k   = blockIdx.y;
    const int n   = blockIdx.x * 256 + threadIdx.x;
    const int idx = g_idx[k * NPOS + n];
    const int b   = n >> 12;
    const int hw  = n & (HW_ - 1);
    const float* crow = cb + ((size_t)(k * SENT + idx)) * DIM;
    const size_t base = ((size_t)(b * 256 + k * DIM)) * HW_ + hw;

    double local = 0.0;
#pragma unroll
    for (int d = 0; d < DIM; d++) {
        float val = __ldg(crow + d);
        float zv  = z[base + (size_t)d * HW_];
        out[base + (size_t)d * HW_] = val;
        float diff = val - zv;
        local += (double)diff * (double)diff;
    }

    __shared__ double sred[256];
    sred[threadIdx.x] = local;
    __syncthreads();
    for (int s = 128; s > 0; s >>= 1) {
        if (threadIdx.x < s) sred[threadIdx.x] += sred[threadIdx.x + s];
        __syncthreads();
    }
    if (threadIdx.x == 0) g_part[k * (NPOS / 256) + blockIdx.x] = sred[0];
}

__global__ void finalize_kernel(float* __restrict__ out, int loss_off) {
    if (loss_off < 0) return;
    __shared__ double sred[256];
    double s = 0.0;
    for (int i = threadIdx.x; i < KCB * (NPOS / 256); i += 256) s += g_part[i];
    sred[threadIdx.x] = s;
    __syncthreads();
    for (int st = 128; st > 0; st >>= 1) {
        if (threadIdx.x < st) sred[threadIdx.x] += sred[threadIdx.x + st];
        __syncthreads();
    }
    if (threadIdx.x == 0) out[loss_off] = (float)(1.25 * sred[0] / (double)ZQ_ELEMS);
}

// ---------------------------------------------------------------------------
extern "C" void kernel_launch(void* const* d_in, const int* in_sizes, int n_in,
                              void* d_out, int out_size) {
    const float* z  = (const float*)d_in[0];
    const float* cb = (const float*)d_in[1];
    if (n_in >= 2 && in_sizes[0] == KCB * SENT * DIM) {
        cb = (const float*)d_in[0];
        z  = (const float*)d_in[1];
    }
    float* out = (float*)d_out;

    int loss_off = -1, idx_off = -1;
    if (out_size == ZQ_ELEMS + 1 + KCB * NPOS) { loss_off = ZQ_ELEMS; idx_off = ZQ_ELEMS + 1; }
    else if (out_size == ZQ_ELEMS + KCB * NPOS) { idx_off = ZQ_ELEMS; }

    const int smemBytes = SMEM_FLOATS * (int)sizeof(float);
    cudaFuncSetAttribute(argmin_tc_kernel, cudaFuncAttributeMaxDynamicSharedMemorySize, smemBytes);

    enorm_kernel<<<KCB * SENT / 256, 256>>>(cb);

    dim3 ga(NPOS / TILE_N, KCB);
    argmin_tc_kernel<<<ga, 256, smemBytes>>>(z, cb, out, idx_off);

    dim3 gs(NPOS / 256, KCB);
    scatter_kernel<<<gs, 256>>>(z, cb, out);

    finalize_kernel<<<1, 256>>>(out, loss_off);
}

// round 5
// speedup vs baseline: 1.7012x; 1.7012x over previous
#include <cuda_runtime.h>
#include <cuda_bf16.h>

#define NPOS   65536
#define HW_    4096
#define KCB    4
#define SENT   1024
#define DIM    64
#define TILE_N 128
#define TILE_S 64
#define NCHUNK 16
#define ZQ_ELEMS 16777216
#define MARGIN 2e-3f
#define CAP    2048
#define PAD    68

// dynamic smem byte offsets
#define OF_CNT  0
#define OF_ABF  1024      // A bf16 swizzled: 128 rows x 128B = 16384
#define OF_BBF  17408     // B bf16 swizzled: 2 x (64 x 128B) = 16384
#define OF_AEX  33792     // A exact fp32 [128][PAD] = 34816
#define OF_ZN   68608     // 128 f32
#define OF_EN   69120     // 2 x 64 f32
#define OF_ROWB 69632     // ull[128] per-row best (dist,idx) key
#define OF_ROWA 70656     // uint[128] per-row approx running min (float bits)
#define OF_CAND 71168     // int[CAP] = 8192  (reused as double[256] for loss)
#define SMEM_TOTAL 79360

// 128B-row swizzle (16B granules): bits[4:6] ^= bits[7:9]
#define SW(x) ((x) ^ (((x) >> 3) & 0x70))

static __device__ __forceinline__ unsigned smem_u32(const void* p) {
    unsigned a;
    asm("{ .reg .u64 t; cvta.to.shared.u64 t, %1; cvt.u32.u64 %0, t; }" : "=r"(a) : "l"(p));
    return a;
}
static __device__ __forceinline__ void cp16(unsigned dst, const void* src) {
    asm volatile("cp.async.cg.shared.global [%0], [%1], 16;" :: "r"(dst), "l"(src));
}
static __device__ __forceinline__ void cp_commit() {
    asm volatile("cp.async.commit_group;" ::: "memory");
}
static __device__ __forceinline__ void cp_wait0() {
    asm volatile("cp.async.wait_group 0;" ::: "memory");
}
static __device__ __forceinline__ void ldsm_x4(unsigned& a0, unsigned& a1, unsigned& a2,
                                               unsigned& a3, unsigned addr) {
    asm volatile("ldmatrix.sync.aligned.m8n8.x4.shared.b16 {%0,%1,%2,%3}, [%4];"
                 : "=r"(a0), "=r"(a1), "=r"(a2), "=r"(a3) : "r"(addr));
}
static __device__ __forceinline__ void ldsm_x2(unsigned& b0, unsigned& b1, unsigned addr) {
    asm volatile("ldmatrix.sync.aligned.m8n8.x2.shared.b16 {%0,%1}, [%2];"
                 : "=r"(b0), "=r"(b1) : "r"(addr));
}
static __device__ __forceinline__ void mma_bf16(float* c, const unsigned* a, const unsigned* b) {
    asm volatile("mma.sync.aligned.m16n8k16.row.col.f32.bf16.bf16.f32 "
                 "{%0,%1,%2,%3}, {%4,%5,%6,%7}, {%8,%9}, {%0,%1,%2,%3};"
                 : "+f"(c[0]), "+f"(c[1]), "+f"(c[2]), "+f"(c[3])
                 : "r"(a[0]), "r"(a[1]), "r"(a[2]), "r"(a[3]), "r"(b[0]), "r"(b[1]));
}
// monotone float->uint (all dists ~64 > 0, but handle sign anyway)
static __device__ __forceinline__ unsigned fkey(float f) {
    unsigned u = __float_as_uint(f);
    return (u & 0x80000000u) ? ~u : (u | 0x80000000u);
}

__device__ __align__(16) float          g_enorm[KCB * SENT];
__device__ __align__(16) __nv_bfloat16  g_cbbf[KCB * SENT * DIM];
__device__ double g_part[KCB * (NPOS / TILE_N)];

// ---------------------------------------------------------------------------
// Per-entry ||e||^2 (reference rounding) + one-time fp32 -> bf16 codebook.
// ---------------------------------------------------------------------------
__global__ void enorm_kernel(const float* __restrict__ cb) {
    int j = blockIdx.x * 256 + threadIdx.x;   // 0..4095
    const float* e = cb + (size_t)j * DIM;
    float s = 0.f;
    unsigned* dst = (unsigned*)g_cbbf + j * (DIM / 2);
#pragma unroll
    for (int d = 0; d < DIM; d += 2) {
        float v0 = e[d], v1 = e[d + 1];
        s = __fadd_rn(s, __fmul_rn(v0, v0));
        s = __fadd_rn(s, __fmul_rn(v1, v1));
        __nv_bfloat162 p = __floats2bfloat162_rn(v0, v1);
        dst[d / 2] = *(unsigned*)&p;
    }
    g_enorm[j] = s;
}

// ---------------------------------------------------------------------------
// bf16 HMMA distance GEMM (cp.async double-buffered) + margin gate +
// deferred exact rescore + fused gather/z_q/loss.
// CTA = 128 positions x 1 codebook; 256 threads, warps 2x4 (64 rows x 16 cols).
// ---------------------------------------------------------------------------
__global__ void __launch_bounds__(256, 2)
vq_main_kernel(const float* __restrict__ z, const float* __restrict__ cb,
               float* __restrict__ out, int idx_off) {
    extern __shared__ char smc[];
    const unsigned smb = smem_u32(smc);
    float*    A_EX  = (float*)(smc + OF_AEX);
    float*    ZN    = (float*)(smc + OF_ZN);
    int*      CNT   = (int*)(smc + OF_CNT);
    int*      CANDS = (int*)(smc + OF_CAND);
    unsigned* ROWA  = (unsigned*)(smc + OF_ROWA);
    unsigned long long* ROWB = (unsigned long long*)(smc + OF_ROWB);

    const int k        = blockIdx.y;
    const int tileBase = blockIdx.x * TILE_N;
    const int b        = tileBase >> 12;
    const int hw0      = tileBase & (HW_ - 1);
    const int tid      = threadIdx.x;
    const int warp     = tid >> 5;
    const int lane     = tid & 31;
    const int g        = lane >> 2;
    const int tg       = lane & 3;
    const int wm       = warp >> 2;   // 0..1 -> rows 64*wm
    const int wn       = warp & 3;    // 0..3 -> cols 16*wn

    if (tid < 128) {
        ROWB[tid] = 0xFFFFFFFFFFFFFFFFull;
        ROWA[tid] = 0xFFFFFFFFu;
    }
    if (tid == 0) *CNT = 0;

    // ---- load z tile: exact fp32 + bf16 swizzled; thread handles half a row ----
    const int  zrow = tid & 127, zhalf = tid >> 7, d0 = zhalf * 32;
    const float* zbase = z + ((size_t)(b * 256 + k * DIM)) * HW_ + hw0;
#pragma unroll
    for (int i = 0; i < 32; i += 2) {
        int d = d0 + i;
        float v0 = zbase[(size_t)d * HW_ + zrow];
        float v1 = zbase[(size_t)(d + 1) * HW_ + zrow];
        A_EX[zrow * PAD + d]     = v0;
        A_EX[zrow * PAD + d + 1] = v1;
        __nv_bfloat162 p = __floats2bfloat162_rn(v0, v1);
        *(unsigned*)(smc + OF_ABF + SW(zrow * 128 + d * 2)) = *(unsigned*)&p;
    }
    __syncthreads();

    // ---- exact znorm: square then sequential fp32 sum (reference order) ----
    if (tid < 128) {
        float s = 0.f;
        for (int d = 0; d < DIM; d++) {
            float v = A_EX[tid * PAD + d];
            s = __fadd_rn(s, __fmul_rn(v, v));
        }
        ZN[tid] = s;
    }

    // ---- prefetch chunk 0 ----
    {
        const char* srcB = (const char*)g_cbbf + ((size_t)k * SENT) * DIM * 2;
        unsigned dstB = smb + OF_BBF;
        cp16(dstB + SW(tid * 16), srcB + tid * 16);
        cp16(dstB + SW(4096 + tid * 16), srcB + 4096 + tid * 16);
        if (tid < 16)
            cp16(smb + OF_EN + tid * 16, (const char*)(g_enorm + k * SENT) + tid * 16);
        cp_commit();
    }

    float bestApp[8];
#pragma unroll
    for (int u = 0; u < 8; u++) bestApp[u] = __int_as_float(0x7f800000);

    const float* cbk = cb + (size_t)k * SENT * DIM;

    for (int c = 0; c < NCHUNK; c++) {
        cp_wait0();
        __syncthreads();
        if (c + 1 < NCHUNK) {
            const char* srcB = (const char*)g_cbbf +
                               ((size_t)(k * SENT + (c + 1) * TILE_S)) * DIM * 2;
            unsigned dstB = smb + OF_BBF + ((c + 1) & 1) * 8192;
            cp16(dstB + SW(tid * 16), srcB + tid * 16);
            cp16(dstB + SW(4096 + tid * 16), srcB + 4096 + tid * 16);
            if (tid < 16)
                cp16(smb + OF_EN + ((c + 1) & 1) * 256 + tid * 16,
                     (const char*)(g_enorm + k * SENT + (c + 1) * TILE_S) + tid * 16);
            cp_commit();
        }

        const unsigned bufB = smb + OF_BBF + (c & 1) * 8192;
        const float*   ENb  = (float*)(smc + OF_EN + (c & 1) * 256);

        // ---- GEMM: warp tile 64 rows x 16 cols, k = 64 (4 x k16) ----
        float acc[4][2][4];
#pragma unroll
        for (int mt = 0; mt < 4; mt++)
#pragma unroll
            for (int nt = 0; nt < 2; nt++)
#pragma unroll
                for (int cc = 0; cc < 4; cc++) acc[mt][nt][cc] = 0.f;

        const int arow = 64 * wm + (lane & 15);
        const int acb  = (lane >> 4) * 16;
        const int brow = 16 * wn + (lane & 7);
        const int bcb  = ((lane >> 3) & 1) * 16;
#pragma unroll
        for (int kk = 0; kk < 4; kk++) {
            unsigned a[4][4], bb[2][2];
#pragma unroll
            for (int mt = 0; mt < 4; mt++)
                ldsm_x4(a[mt][0], a[mt][1], a[mt][2], a[mt][3],
                        smb + OF_ABF + SW((arow + 16 * mt) * 128 + kk * 32 + acb));
#pragma unroll
            for (int nt = 0; nt < 2; nt++)
                ldsm_x2(bb[nt][0], bb[nt][1],
                        bufB + SW((brow + 8 * nt) * 128 + kk * 32 + bcb));
#pragma unroll
            for (int mt = 0; mt < 4; mt++)
#pragma unroll
                for (int nt = 0; nt < 2; nt++)
                    mma_bf16(acc[mt][nt], a[mt], bb[nt]);
        }

        // ---- epilogue: approx dists, slice min, gate, record candidates ----
#pragma unroll
        for (int mt = 0; mt < 4; mt++) {
            int r0 = 64 * wm + 16 * mt + g;
            float zn0 = ZN[r0], zn1 = ZN[r0 + 8];
#pragma unroll
            for (int h = 0; h < 2; h++) {
                int row = r0 + 8 * h;
                float znv = h ? zn1 : zn0;
                float dv[4];
#pragma unroll
                for (int nt = 0; nt < 2; nt++) {
                    int col0 = 16 * wn + 8 * nt + 2 * tg;
                    dv[nt * 2 + 0] = __fmaf_rn(-2.f, acc[mt][nt][2 * h + 0], znv + ENb[col0]);
                    dv[nt * 2 + 1] = __fmaf_rn(-2.f, acc[mt][nt][2 * h + 1], znv + ENb[col0 + 1]);
                }
                float m = fminf(fminf(dv[0], dv[1]), fminf(dv[2], dv[3]));
                m = fminf(m, __shfl_xor_sync(0xffffffffu, m, 1));
                m = fminf(m, __shfl_xor_sync(0xffffffffu, m, 2));
                int slot = mt * 2 + h;
                float ra = __uint_as_float(ROWA[row]);      // NaN-init: fminf ignores
                float gate = fminf(bestApp[slot], fminf(ra, m)) + MARGIN;
#pragma unroll
                for (int q = 0; q < 4; q++) {
                    if (dv[q] < gate) {
                        int jg = c * TILE_S + 16 * wn + 8 * (q >> 1) + 2 * tg + (q & 1);
                        int pos = atomicAdd(CNT, 1);
                        if (pos < CAP) {
                            CANDS[pos] = (row << 10) | jg;
                        } else {  // overflow: inline exact rescore from global
                            const float* e = cbk + (size_t)jg * DIM;
                            float dot = 0.f;
#pragma unroll 8
                            for (int d = 0; d < DIM; d++)
                                dot = __fmaf_rn(A_EX[row * PAD + d], e[d], dot);
                            float de = __fsub_rn(__fadd_rn(ZN[row], g_enorm[k * SENT + jg]),
                                                 __fmul_rn(2.0f, dot));
                            atomicMin(&ROWB[row],
                                      ((unsigned long long)fkey(de) << 32) | (unsigned)jg);
                        }
                    }
                }
                bestApp[slot] = fminf(bestApp[slot], m);
                if (tg == 0) atomicMin(&ROWA[row], __float_as_uint(m));
            }
        }
    }
    __syncthreads();

    // ---- deferred warp-parallel exact rescore (R1 rounding, (dist,idx) key) ----
    int cnt = *CNT; if (cnt > CAP) cnt = CAP;
    for (int ci = tid; ci < cnt; ci += 256) {
        int cd  = CANDS[ci];
        int row = cd >> 10, jg = cd & 1023;
        const float* e = cbk + (size_t)jg * DIM;
        float dot = 0.f;
#pragma unroll 8
        for (int d = 0; d < DIM; d++)
            dot = __fmaf_rn(A_EX[row * PAD + d], e[d], dot);
        float de = __fsub_rn(__fadd_rn(ZN[row], g_enorm[k * SENT + jg]),
                             __fmul_rn(2.0f, dot));
        atomicMin(&ROWB[row], ((unsigned long long)fkey(de) << 32) | (unsigned)jg);
    }
    __syncthreads();

    // ---- outputs: indices, z_q gather, loss partial ----
    if (tid < 128 && idx_off >= 0)
        out[(size_t)idx_off + (size_t)k * NPOS + tileBase + tid] = (float)(ROWB[tid] & 1023u);

    const int bestI = (int)(ROWB[zrow] & 1023u);
    const float* crow = cb + ((size_t)(k * SENT + bestI)) * DIM;
    const size_t obase = ((size_t)(b * 256 + k * DIM)) * HW_ + hw0 + zrow;
    double loc = 0.0;
#pragma unroll
    for (int i = 0; i < 32; i++) {
        int d = d0 + i;
        float val = __ldg(crow + d);
        float zv  = A_EX[zrow * PAD + d];
        out[obase + (size_t)d * HW_] = val;     // coalesced across zrow
        float diff = val - zv;
        loc += (double)diff * (double)diff;
    }
    __syncthreads();                            // CANDS no longer needed
    double* sred = (double*)(smc + OF_CAND);
    sred[tid] = loc;
    __syncthreads();
    for (int s = 128; s > 0; s >>= 1) {
        if (tid < s) sred[tid] += sred[tid + s];
        __syncthreads();
    }
    if (tid == 0) g_part[k * (NPOS / TILE_N) + blockIdx.x] = sred[0];
}

// ---------------------------------------------------------------------------
__global__ void finalize_kernel(float* __restrict__ out, int loss_off) {
    if (loss_off < 0) return;
    __shared__ double sred[256];
    double s = 0.0;
    for (int i = threadIdx.x; i < KCB * (NPOS / TILE_N); i += 256) s += g_part[i];
    sred[threadIdx.x] = s;
    __syncthreads();
    for (int st = 128; st > 0; st >>= 1) {
        if (threadIdx.x < st) sred[threadIdx.x] += sred[threadIdx.x + st];
        __syncthreads();
    }
    if (threadIdx.x == 0) out[loss_off] = (float)(1.25 * sred[0] / (double)ZQ_ELEMS);
}

// ---------------------------------------------------------------------------
extern "C" void kernel_launch(void* const* d_in, const int* in_sizes, int n_in,
                              void* d_out, int out_size) {
    const float* z  = (const float*)d_in[0];
    const float* cb = (const float*)d_in[1];
    if (n_in >= 2 && in_sizes[0] == KCB * SENT * DIM) {
        cb = (const float*)d_in[0];
        z  = (const float*)d_in[1];
    }
    float* out = (float*)d_out;

    int loss_off = -1, idx_off = -1;
    if (out_size == ZQ_ELEMS + 1 + KCB * NPOS) { loss_off = ZQ_ELEMS; idx_off = ZQ_ELEMS + 1; }
    else if (out_size == ZQ_ELEMS + KCB * NPOS) { idx_off = ZQ_ELEMS; }

    cudaFuncSetAttribute(vq_main_kernel, cudaFuncAttributeMaxDynamicSharedMemorySize, SMEM_TOTAL);

    enorm_kernel<<<KCB * SENT / 256, 256>>>(cb);

    dim3 ga(NPOS / TILE_N, KCB);
    vq_main_kernel<<<ga, 256, SMEM_TOTAL>>>(z, cb, out, idx_off);

    finalize_kernel<<<1, 256>>>(out, loss_off);
}

// round 6
// speedup vs baseline: 2.1454x; 1.2611x over previous
#include <cuda_runtime.h>
#include <cuda_bf16.h>

#define NPOS   65536
#define HW_    4096
#define KCB    4
#define SENT   1024
#define DIM    64
#define TILE_N 128
#define TILE_S 64
#define NCHUNK 16
#define ZQ_ELEMS 16777216
#define CAPW   256
#define PAD    68

// dynamic smem byte offsets
#define OF_WCNT 0         // int[8] per-warp candidate counts
#define OF_ABF  1024      // A bf16 swizzled: 128 rows x 128B = 16384
#define OF_BBF  17408     // B bf16 swizzled: 2 x (64 x 128B) = 16384
#define OF_AEX  33792     // A exact fp32 [128][PAD] = 34816
#define OF_ZN   68608     // 128 f32
#define OF_EN   69120     // 2 x 64 f32
#define OF_ROWB 69632     // ull[128] per-row best (dist,idx) key
#define OF_ROWA 70656     // uint[128] per-row approx running min (float bits)
#define OF_MROW 71168     // float[128] per-row certified margin
#define OF_CAND 71680     // int[8*CAPW] = 8192 (reused as double[256] for loss)
#define SMEM_TOTAL 79872

// 128B-row swizzle (16B granules): bits[4:6] ^= bits[7:9]
#define SW(x) ((x) ^ (((x) >> 3) & 0x70))

static __device__ __forceinline__ unsigned smem_u32(const void* p) {
    unsigned a;
    asm("{ .reg .u64 t; cvta.to.shared.u64 t, %1; cvt.u32.u64 %0, t; }" : "=r"(a) : "l"(p));
    return a;
}
static __device__ __forceinline__ void cp16(unsigned dst, const void* src) {
    asm volatile("cp.async.cg.shared.global [%0], [%1], 16;" :: "r"(dst), "l"(src));
}
static __device__ __forceinline__ void cp_commit() {
    asm volatile("cp.async.commit_group;" ::: "memory");
}
static __device__ __forceinline__ void cp_wait0() {
    asm volatile("cp.async.wait_group 0;" ::: "memory");
}
static __device__ __forceinline__ void ldsm_x4(unsigned& a0, unsigned& a1, unsigned& a2,
                                               unsigned& a3, unsigned addr) {
    asm volatile("ldmatrix.sync.aligned.m8n8.x4.shared.b16 {%0,%1,%2,%3}, [%4];"
                 : "=r"(a0), "=r"(a1), "=r"(a2), "=r"(a3) : "r"(addr));
}
static __device__ __forceinline__ void ldsm_x2(unsigned& b0, unsigned& b1, unsigned addr) {
    asm volatile("ldmatrix.sync.aligned.m8n8.x2.shared.b16 {%0,%1}, [%2];"
                 : "=r"(b0), "=r"(b1) : "r"(addr));
}
static __device__ __forceinline__ void mma_bf16(float* c, const unsigned* a, const unsigned* b) {
    asm volatile("mma.sync.aligned.m16n8k16.row.col.f32.bf16.bf16.f32 "
                 "{%0,%1,%2,%3}, {%4,%5,%6,%7}, {%8,%9}, {%0,%1,%2,%3};"
                 : "+f"(c[0]), "+f"(c[1]), "+f"(c[2]), "+f"(c[3])
                 : "r"(a[0]), "r"(a[1]), "r"(a[2]), "r"(a[3]), "r"(b[0]), "r"(b[1]));
}
// monotone float->uint
static __device__ __forceinline__ unsigned fkey(float f) {
    unsigned u = __float_as_uint(f);
    return (u & 0x80000000u) ? ~u : (u | 0x80000000u);
}

__device__ __align__(16) float          g_enorm[KCB * SENT];
__device__ __align__(16) __nv_bfloat16  g_cbbf[KCB * SENT * DIM];
__device__ double   g_part[KCB * (NPOS / TILE_N)];
__device__ unsigned g_emax2[KCB] = {0, 0, 0, 0};   // max ||e||^2 per codebook (float bits)

// ---------------------------------------------------------------------------
// Per-entry ||e||^2 (reference rounding), bf16 codebook, per-k max norm^2.
// ---------------------------------------------------------------------------
__global__ void enorm_kernel(const float* __restrict__ cb) {
    int j = blockIdx.x * 256 + threadIdx.x;   // 0..4095
    const float* e = cb + (size_t)j * DIM;
    float s = 0.f;
    unsigned* dst = (unsigned*)g_cbbf + j * (DIM / 2);
#pragma unroll
    for (int d = 0; d < DIM; d += 2) {
        float v0 = e[d], v1 = e[d + 1];
        s = __fadd_rn(s, __fmul_rn(v0, v0));
        s = __fadd_rn(s, __fmul_rn(v1, v1));
        __nv_bfloat162 p = __floats2bfloat162_rn(v0, v1);
        dst[d / 2] = *(unsigned*)&p;
    }
    g_enorm[j] = s;
    atomicMax(&g_emax2[j >> 10], __float_as_uint(s));   // s >= 0: uint cmp == float cmp
}

// ---------------------------------------------------------------------------
// bf16 HMMA distance GEMM + certified-margin gate (ballot-allocated per-warp
// candidate lists, no hot-path atomics) + deferred exact rescore + fused
// gather/z_q/loss. CTA = 128 positions x 1 codebook; 256 threads.
// ---------------------------------------------------------------------------
__global__ void __launch_bounds__(256, 2)
vq_main_kernel(const float* __restrict__ z, const float* __restrict__ cb,
               float* __restrict__ out, int idx_off) {
    extern __shared__ char smc[];
    const unsigned smb = smem_u32(smc);
    float*    A_EX  = (float*)(smc + OF_AEX);
    float*    ZN    = (float*)(smc + OF_ZN);
    float*    MROW  = (float*)(smc + OF_MROW);
    int*      WCNTS = (int*)(smc + OF_WCNT);
    int*      CANDS = (int*)(smc + OF_CAND);
    unsigned* ROWA  = (unsigned*)(smc + OF_ROWA);
    unsigned long long* ROWB = (unsigned long long*)(smc + OF_ROWB);

    const int k        = blockIdx.y;
    const int tileBase = blockIdx.x * TILE_N;
    const int b        = tileBase >> 12;
    const int hw0      = tileBase & (HW_ - 1);
    const int tid      = threadIdx.x;
    const int warp     = tid >> 5;
    const int lane     = tid & 31;
    const int g        = lane >> 2;
    const int tg       = lane & 3;
    const int wm       = warp >> 2;   // rows 64*wm
    const int wn       = warp & 3;    // cols 16*wn
    const unsigned ltmask = (1u << lane) - 1u;

    if (tid < 128) {
        ROWB[tid] = 0xFFFFFFFFFFFFFFFFull;
        ROWA[tid] = 0xFFFFFFFFu;
    }

    // ---- load z tile: exact fp32 + bf16 swizzled; thread handles half a row ----
    const int  zrow = tid & 127, zhalf = tid >> 7, d0 = zhalf * 32;
    const float* zbase = z + ((size_t)(b * 256 + k * DIM)) * HW_ + hw0;
#pragma unroll
    for (int i = 0; i < 32; i += 2) {
        int d = d0 + i;
        float v0 = zbase[(size_t)d * HW_ + zrow];
        float v1 = zbase[(size_t)(d + 1) * HW_ + zrow];
        A_EX[zrow * PAD + d]     = v0;
        A_EX[zrow * PAD + d + 1] = v1;
        __nv_bfloat162 p = __floats2bfloat162_rn(v0, v1);
        *(unsigned*)(smc + OF_ABF + SW(zrow * 128 + d * 2)) = *(unsigned*)&p;
    }
    __syncthreads();

    // ---- exact znorm (reference rounding) + certified per-row margin ----
    if (tid < 128) {
        float s = 0.f;
        for (int d = 0; d < DIM; d++) {
            float v = A_EX[tid * PAD + d];
            s = __fadd_rn(s, __fmul_rn(v, v));
        }
        ZN[tid] = s;
        float emax2 = __uint_as_float(g_emax2[k]);
        // |dist_approx - dist_exact| <= 2^-7 * |z| * |e|;  gate needs 2x + slack
        MROW[tid] = 0.0165f * sqrtf(s * emax2) + 2e-5f;
    }

    // ---- prefetch chunk 0 ----
    {
        const char* srcB = (const char*)g_cbbf + ((size_t)k * SENT) * DIM * 2;
        unsigned dstB = smb + OF_BBF;
        cp16(dstB + SW(tid * 16), srcB + tid * 16);
        cp16(dstB + SW(4096 + tid * 16), srcB + 4096 + tid * 16);
        if (tid < 16)
            cp16(smb + OF_EN + tid * 16, (const char*)(g_enorm + k * SENT) + tid * 16);
        cp_commit();
    }

    float bestApp[8];
#pragma unroll
    for (int u = 0; u < 8; u++) bestApp[u] = __int_as_float(0x7f800000);

    int warpCnt = 0;                               // uniform across warp
    int* WCAND = CANDS + warp * CAPW;
    const float* cbk = cb + (size_t)k * SENT * DIM;

    for (int c = 0; c < NCHUNK; c++) {
        cp_wait0();
        __syncthreads();
        if (c + 1 < NCHUNK) {
            const char* srcB = (const char*)g_cbbf +
                               ((size_t)(k * SENT + (c + 1) * TILE_S)) * DIM * 2;
            unsigned dstB = smb + OF_BBF + ((c + 1) & 1) * 8192;
            cp16(dstB + SW(tid * 16), srcB + tid * 16);
            cp16(dstB + SW(4096 + tid * 16), srcB + 4096 + tid * 16);
            if (tid < 16)
                cp16(smb + OF_EN + ((c + 1) & 1) * 256 + tid * 16,
                     (const char*)(g_enorm + k * SENT + (c + 1) * TILE_S) + tid * 16);
            cp_commit();
        }

        const unsigned bufB = smb + OF_BBF + (c & 1) * 8192;
        const float*   ENb  = (float*)(smc + OF_EN + (c & 1) * 256);

        // ---- GEMM: warp tile 64 rows x 16 cols, k = 64 (4 x k16) ----
        float acc[4][2][4];
#pragma unroll
        for (int mt = 0; mt < 4; mt++)
#pragma unroll
            for (int nt = 0; nt < 2; nt++)
#pragma unroll
                for (int cc = 0; cc < 4; cc++) acc[mt][nt][cc] = 0.f;

        const int arow = 64 * wm + (lane & 15);
        const int acb  = (lane >> 4) * 16;
        const int brow = 16 * wn + (lane & 7);
        const int bcb  = ((lane >> 3) & 1) * 16;
#pragma unroll
        for (int kk = 0; kk < 4; kk++) {
            unsigned a[4][4], bb[2][2];
#pragma unroll
            for (int mt = 0; mt < 4; mt++)
                ldsm_x4(a[mt][0], a[mt][1], a[mt][2], a[mt][3],
                        smb + OF_ABF + SW((arow + 16 * mt) * 128 + kk * 32 + acb));
#pragma unroll
            for (int nt = 0; nt < 2; nt++)
                ldsm_x2(bb[nt][0], bb[nt][1],
                        bufB + SW((brow + 8 * nt) * 128 + kk * 32 + bcb));
#pragma unroll
            for (int mt = 0; mt < 4; mt++)
#pragma unroll
                for (int nt = 0; nt < 2; nt++)
                    mma_bf16(acc[mt][nt], a[mt], bb[nt]);
        }

        // ---- epilogue: approx dists, running row min, certified gate ----
#pragma unroll
        for (int mt = 0; mt < 4; mt++) {
            int r0 = 64 * wm + 16 * mt + g;
#pragma unroll
            for (int h = 0; h < 2; h++) {
                int row = r0 + 8 * h;
                float znv = ZN[row];
                float dv[4];
#pragma unroll
                for (int nt = 0; nt < 2; nt++) {
                    int col0 = 16 * wn + 8 * nt + 2 * tg;
                    dv[nt * 2 + 0] = __fmaf_rn(-2.f, acc[mt][nt][2 * h + 0], znv + ENb[col0]);
                    dv[nt * 2 + 1] = __fmaf_rn(-2.f, acc[mt][nt][2 * h + 1], znv + ENb[col0 + 1]);
                }
                float ml = fminf(fminf(dv[0], dv[1]), fminf(dv[2], dv[3]));
                float m  = fminf(ml, __shfl_xor_sync(0xffffffffu, ml, 1));
                m        = fminf(m,  __shfl_xor_sync(0xffffffffu, m, 2));
                int slot = mt * 2 + h;
                float ra   = __uint_as_float(ROWA[row]);   // NaN-init ignored by fminf
                float gate = fminf(bestApp[slot], fminf(ra, m)) + MROW[row];

                // fast path: skip slot if no lane has a candidate
                if (__ballot_sync(0xffffffffu, ml < gate)) {
#pragma unroll
                    for (int q = 0; q < 4; q++) {
                        bool pr = dv[q] < gate;
                        unsigned mask = __ballot_sync(0xffffffffu, pr);
                        if (mask) {
                            int pos = warpCnt + __popc(mask & ltmask);
                            if (pr) {
                                int jg = c * TILE_S + 16 * wn + 8 * (q >> 1) + 2 * tg + (q & 1);
                                if (pos < CAPW) {
                                    WCAND[pos] = (row << 10) | jg;
                                } else {   // rare overflow: inline exact rescore
                                    const float* e = cbk + (size_t)jg * DIM;
                                    float dot = 0.f;
#pragma unroll 8
                                    for (int d = 0; d < DIM; d++)
                                        dot = __fmaf_rn(A_EX[row * PAD + d], e[d], dot);
                                    float de = __fsub_rn(
                                        __fadd_rn(ZN[row], g_enorm[k * SENT + jg]),
                                        __fmul_rn(2.0f, dot));
                                    atomicMin(&ROWB[row],
                                              ((unsigned long long)fkey(de) << 32) | (unsigned)jg);
                                }
                            }
                            warpCnt += __popc(mask);
                        }
                    }
                }
                bestApp[slot] = fminf(bestApp[slot], m);
                if (tg == 0) atomicMin(&ROWA[row], __float_as_uint(m));
            }
        }
    }
    if (lane == 0) WCNTS[warp] = warpCnt;
    __syncthreads();

    // ---- deferred exact rescore (R1 sequential-FMA rounding; (dist,idx) key) ----
#pragma unroll
    for (int w = 0; w < 8; w++) {
        int cw = WCNTS[w]; if (cw > CAPW) cw = CAPW;
        for (int ci = tid; ci < cw; ci += 256) {
            int cd  = CANDS[w * CAPW + ci];
            int row = cd >> 10, jg = cd & 1023;
            const float* e = cbk + (size_t)jg * DIM;
            float dot = 0.f;
#pragma unroll 8
            for (int d = 0; d < DIM; d++)
                dot = __fmaf_rn(A_EX[row * PAD + d], e[d], dot);
            float de = __fsub_rn(__fadd_rn(ZN[row], g_enorm[k * SENT + jg]),
                                 __fmul_rn(2.0f, dot));
            atomicMin(&ROWB[row], ((unsigned long long)fkey(de) << 32) | (unsigned)jg);
        }
    }
    __syncthreads();

    // ---- outputs: indices, z_q gather, loss partial ----
    if (tid < 128 && idx_off >= 0)
        out[(size_t)idx_off + (size_t)k * NPOS + tileBase + tid] = (float)(ROWB[tid] & 1023u);

    const int bestI = (int)(ROWB[zrow] & 1023u);
    const float* crow = cb + ((size_t)(k * SENT + bestI)) * DIM;
    const size_t obase = ((size_t)(b * 256 + k * DIM)) * HW_ + hw0 + zrow;
    double loc = 0.0;
#pragma unroll
    for (int i = 0; i < 32; i++) {
        int d = d0 + i;
        float val = __ldg(crow + d);
        float zv  = A_EX[zrow * PAD + d];
        out[obase + (size_t)d * HW_] = val;     // coalesced across zrow
        float diff = val - zv;
        loc += (double)diff * (double)diff;
    }
    __syncthreads();                            // CANDS no longer needed
    double* sred = (double*)(smc + OF_CAND);
    sred[tid] = loc;
    __syncthreads();
    for (int s = 128; s > 0; s >>= 1) {
        if (tid < s) sred[tid] += sred[tid + s];
        __syncthreads();
    }
    if (tid == 0) g_part[k * (NPOS / TILE_N) + blockIdx.x] = sred[0];
}

// ---------------------------------------------------------------------------
__global__ void finalize_kernel(float* __restrict__ out, int loss_off) {
    if (loss_off < 0) return;
    __shared__ double sred[256];
    double s = 0.0;
    for (int i = threadIdx.x; i < KCB * (NPOS / TILE_N); i += 256) s += g_part[i];
    sred[threadIdx.x] = s;
    __syncthreads();
    for (int st = 128; st > 0; st >>= 1) {
        if (threadIdx.x < st) sred[threadIdx.x] += sred[threadIdx.x + st];
        __syncthreads();
    }
    if (threadIdx.x == 0) out[loss_off] = (float)(1.25 * sred[0] / (double)ZQ_ELEMS);
}

// ---------------------------------------------------------------------------
extern "C" void kernel_launch(void* const* d_in, const int* in_sizes, int n_in,
                              void* d_out, int out_size) {
    const float* z  = (const float*)d_in[0];
    const float* cb = (const float*)d_in[1];
    if (n_in >= 2 && in_sizes[0] == KCB * SENT * DIM) {
        cb = (const float*)d_in[0];
        z  = (const float*)d_in[1];
    }
    float* out = (float*)d_out;

    int loss_off = -1, idx_off = -1;
    if (out_size == ZQ_ELEMS + 1 + KCB * NPOS) { loss_off = ZQ_ELEMS; idx_off = ZQ_ELEMS + 1; }
    else if (out_size == ZQ_ELEMS + KCB * NPOS) { idx_off = ZQ_ELEMS; }

    cudaFuncSetAttribute(vq_main_kernel, cudaFuncAttributeMaxDynamicSharedMemorySize, SMEM_TOTAL);

    enorm_kernel<<<KCB * SENT / 256, 256>>>(cb);

    dim3 ga(NPOS / TILE_N, KCB);
    vq_main_kernel<<<ga, 256, SMEM_TOTAL>>>(z, cb, out, idx_off);

    finalize_kernel<<<1, 256>>>(out, loss_off);
}

// round 7
// speedup vs baseline: 2.6862x; 1.2521x over previous
#include <cuda_runtime.h>
#include <cuda_fp16.h>

#define NPOS   65536
#define HW_    4096
#define KCB    4
#define SENT   1024
#define DIM    64
#define TILE_N 128
#define TILE_S 64
#define NCHUNK 16
#define ZQ_ELEMS 16777216
#define CAPW   256
#define PAD    68

// dynamic smem byte offsets
#define OF_WCNT 0         // int[8] per-warp candidate counts
#define OF_ABF  1024      // A fp16 swizzled: 128 rows x 128B = 16384
#define OF_BBF  17408     // B fp16 swizzled: 2 x (64 x 128B) = 16384
#define OF_AEX  33792     // A exact fp32 [128][PAD] = 34816
#define OF_ZN   68608     // 128 f32
#define OF_EN   69120     // 2 x 64 f32  (-en/2 per stage)
#define OF_ROWB 69632     // ull[128] per-row best (dist,idx) key
#define OF_ROWA 70656     // uint[128] per-row running acc-max (monotone bits)
#define OF_MROW 71168     // float[128] per-row certified margin (acc space)
#define OF_CAND 71680     // int[8*CAPW] = 8192 (reused as double[256] for loss)
#define SMEM_TOTAL 79872

// 128B-row swizzle (16B granules): bits[4:6] ^= bits[7:9]
#define SW(x) ((x) ^ (((x) >> 3) & 0x70))

static __device__ __forceinline__ unsigned smem_u32(const void* p) {
    unsigned a;
    asm("{ .reg .u64 t; cvta.to.shared.u64 t, %1; cvt.u32.u64 %0, t; }" : "=r"(a) : "l"(p));
    return a;
}
static __device__ __forceinline__ void cp16(unsigned dst, const void* src) {
    asm volatile("cp.async.cg.shared.global [%0], [%1], 16;" :: "r"(dst), "l"(src));
}
static __device__ __forceinline__ void cp_commit() {
    asm volatile("cp.async.commit_group;" ::: "memory");
}
static __device__ __forceinline__ void cp_wait0() {
    asm volatile("cp.async.wait_group 0;" ::: "memory");
}
static __device__ __forceinline__ void ldsm_x4(unsigned& a0, unsigned& a1, unsigned& a2,
                                               unsigned& a3, unsigned addr) {
    asm volatile("ldmatrix.sync.aligned.m8n8.x4.shared.b16 {%0,%1,%2,%3}, [%4];"
                 : "=r"(a0), "=r"(a1), "=r"(a2), "=r"(a3) : "r"(addr));
}
static __device__ __forceinline__ void ldsm_x2(unsigned& b0, unsigned& b1, unsigned addr) {
    asm volatile("ldmatrix.sync.aligned.m8n8.x2.shared.b16 {%0,%1}, [%2];"
                 : "=r"(b0), "=r"(b1) : "r"(addr));
}
static __device__ __forceinline__ void mma_fp16(float* c, const unsigned* a, const unsigned* b) {
    asm volatile("mma.sync.aligned.m16n8k16.row.col.f32.f16.f16.f32 "
                 "{%0,%1,%2,%3}, {%4,%5,%6,%7}, {%8,%9}, {%0,%1,%2,%3};"
                 : "+f"(c[0]), "+f"(c[1]), "+f"(c[2]), "+f"(c[3])
                 : "r"(a[0]), "r"(a[1]), "r"(a[2]), "r"(a[3]), "r"(b[0]), "r"(b[1]));
}
// monotone float<->uint (order-preserving)
static __device__ __forceinline__ unsigned fkey(float f) {
    unsigned u = __float_as_uint(f);
    return (u & 0x80000000u) ? ~u : (u | 0x80000000u);
}
static __device__ __forceinline__ float unfkey(unsigned u) {
    unsigned v = (u & 0x80000000u) ? (u & 0x7fffffffu) : ~u;
    return __uint_as_float(v);
}

__device__ __align__(16) float  g_enorm[KCB * SENT];   // exact +||e||^2 (reference rounding)
__device__ __align__(16) float  g_enh[KCB * SENT];     // -||e||^2 / 2 (acc init)
__device__ __align__(16) __half g_cbh[KCB * SENT * DIM];
__device__ double   g_part[KCB * (NPOS / TILE_N)];
__device__ unsigned g_emax2[KCB] = {0, 0, 0, 0};       // max ||e||^2 per codebook

// ---------------------------------------------------------------------------
__global__ void enorm_kernel(const float* __restrict__ cb) {
    int j = blockIdx.x * 256 + threadIdx.x;   // 0..4095
    const float* e = cb + (size_t)j * DIM;
    float s = 0.f;
    unsigned* dst = (unsigned*)g_cbh + j * (DIM / 2);
#pragma unroll
    for (int d = 0; d < DIM; d += 2) {
        float v0 = e[d], v1 = e[d + 1];
        s = __fadd_rn(s, __fmul_rn(v0, v0));
        s = __fadd_rn(s, __fmul_rn(v1, v1));
        __half2 p = __floats2half2_rn(v0, v1);
        dst[d / 2] = *(unsigned*)&p;
    }
    g_enorm[j] = s;
    g_enh[j]   = -0.5f * s;
    atomicMax(&g_emax2[j >> 10], __float_as_uint(s));
}

// ---------------------------------------------------------------------------
// fp16 HMMA distance GEMM, A fragments register-resident for the whole kernel,
// acc initialized to -en/2 (epilogue = pure max + certified gate), ballot-
// allocated candidates, deferred exact rescore, fused gather/z_q/loss.
// CTA = 128 positions x 1 codebook; 256 threads; warp tile 32 rows x 32 cols.
// ---------------------------------------------------------------------------
__global__ void __launch_bounds__(256, 2)
vq_main_kernel(const float* __restrict__ z, const float* __restrict__ cb,
               float* __restrict__ out, int idx_off) {
    extern __shared__ char smc[];
    const unsigned smb = smem_u32(smc);
    float*    A_EX  = (float*)(smc + OF_AEX);
    float*    ZN    = (float*)(smc + OF_ZN);
    float*    MROW  = (float*)(smc + OF_MROW);
    int*      WCNTS = (int*)(smc + OF_WCNT);
    int*      CANDS = (int*)(smc + OF_CAND);
    unsigned* ROWA  = (unsigned*)(smc + OF_ROWA);
    unsigned long long* ROWB = (unsigned long long*)(smc + OF_ROWB);

    const int k        = blockIdx.y;
    const int tileBase = blockIdx.x * TILE_N;
    const int b        = tileBase >> 12;
    const int hw0      = tileBase & (HW_ - 1);
    const int tid      = threadIdx.x;
    const int warp     = tid >> 5;
    const int lane     = tid & 31;
    const int g        = lane >> 2;
    const int tg       = lane & 3;
    const int wm       = warp >> 1;   // 0..3 -> rows 32*wm
    const int wn       = warp & 1;    // 0..1 -> cols 32*wn
    const unsigned ltmask = (1u << lane) - 1u;

    if (tid < 128) {
        ROWB[tid] = 0xFFFFFFFFFFFFFFFFull;
        ROWA[tid] = 0u;                       // unfkey(0) = NaN; fmaxf ignores
    }

    // ---- prefetch chunk 0 (B fp16 + -en/2) ----
    {
        const char* srcB = (const char*)g_cbh + ((size_t)k * SENT) * DIM * 2;
        unsigned dstB = smb + OF_BBF;
        cp16(dstB + SW(tid * 16), srcB + tid * 16);
        cp16(dstB + SW(4096 + tid * 16), srcB + 4096 + tid * 16);
        if (tid < 16)
            cp16(smb + OF_EN + tid * 16, (const char*)(g_enh + k * SENT) + tid * 16);
        cp_commit();
    }

    // ---- load z tile: exact fp32 + fp16 swizzled; thread handles half a row ----
    const int  zrow = tid & 127, zhalf = tid >> 7, d0 = zhalf * 32;
    const float* zbase = z + ((size_t)(b * 256 + k * DIM)) * HW_ + hw0;
#pragma unroll
    for (int i = 0; i < 32; i += 2) {
        int d = d0 + i;
        float v0 = zbase[(size_t)d * HW_ + zrow];
        float v1 = zbase[(size_t)(d + 1) * HW_ + zrow];
        A_EX[zrow * PAD + d]     = v0;
        A_EX[zrow * PAD + d + 1] = v1;
        __half2 p = __floats2half2_rn(v0, v1);
        *(unsigned*)(smc + OF_ABF + SW(zrow * 128 + d * 2)) = *(unsigned*)&p;
    }
    __syncthreads();

    // ---- exact znorm (reference rounding) + certified acc-space margin M/2 ----
    if (tid < 128) {
        float s = 0.f;
        for (int d = 0; d < DIM; d++) {
            float v = A_EX[tid * PAD + d];
            s = __fadd_rn(s, __fmul_rn(v, v));
        }
        ZN[tid] = s;
        float emax2 = __uint_as_float(g_emax2[k]);
        // |acc_err| <= 2^-10 |z||e| (fp16 ops) + ref-rounding; x2 safety:
        MROW[tid] = 0.002f * sqrtf(s * emax2) + 3e-5f;
    }

    // ---- preload ALL A fragments into registers (once) ----
    unsigned afr[2][4][4];
    {
        const int arow = 32 * wm + (lane & 15);
        const int acb  = (lane >> 4) * 16;
#pragma unroll
        for (int mt = 0; mt < 2; mt++)
#pragma unroll
            for (int kk = 0; kk < 4; kk++)
                ldsm_x4(afr[mt][kk][0], afr[mt][kk][1], afr[mt][kk][2], afr[mt][kk][3],
                        smb + OF_ABF + SW((arow + 16 * mt) * 128 + kk * 32 + acb));
    }

    float bestApp[4];
#pragma unroll
    for (int u = 0; u < 4; u++) bestApp[u] = -__int_as_float(0x7f800000);

    int warpCnt = 0;
    int* WCAND = CANDS + warp * CAPW;
    const float* cbk = cb + (size_t)k * SENT * DIM;
    const int brow = 32 * wn + (lane & 7);
    const int bcb  = ((lane >> 3) & 1) * 16;

    for (int c = 0; c < NCHUNK; c++) {
        cp_wait0();
        __syncthreads();
        if (c + 1 < NCHUNK) {
            const char* srcB = (const char*)g_cbh +
                               ((size_t)(k * SENT + (c + 1) * TILE_S)) * DIM * 2;
            unsigned dstB = smb + OF_BBF + ((c + 1) & 1) * 8192;
            cp16(dstB + SW(tid * 16), srcB + tid * 16);
            cp16(dstB + SW(4096 + tid * 16), srcB + 4096 + tid * 16);
            if (tid < 16)
                cp16(smb + OF_EN + ((c + 1) & 1) * 256 + tid * 16,
                     (const char*)(g_enh + k * SENT + (c + 1) * TILE_S) + tid * 16);
            cp_commit();
        }

        const unsigned bufB = smb + OF_BBF + (c & 1) * 8192;
        const float*   ENHb = (float*)(smc + OF_EN + (c & 1) * 256);

        // ---- init acc = -en/2 for this chunk's columns ----
        float acc[2][4][4];
#pragma unroll
        for (int nt = 0; nt < 4; nt++) {
            float2 ee = *(const float2*)&ENHb[32 * wn + 8 * nt + 2 * tg];
#pragma unroll
            for (int mt = 0; mt < 2; mt++) {
                acc[mt][nt][0] = ee.x; acc[mt][nt][1] = ee.y;
                acc[mt][nt][2] = ee.x; acc[mt][nt][3] = ee.y;
            }
        }

        // ---- GEMM: warp tile 32 rows x 32 cols; A from registers ----
#pragma unroll
        for (int kk = 0; kk < 4; kk++) {
            unsigned bb[4][2];
#pragma unroll
            for (int nt = 0; nt < 4; nt++)
                ldsm_x2(bb[nt][0], bb[nt][1],
                        bufB + SW((brow + 8 * nt) * 128 + kk * 32 + bcb));
#pragma unroll
            for (int mt = 0; mt < 2; mt++)
#pragma unroll
                for (int nt = 0; nt < 4; nt++)
                    mma_fp16(acc[mt][nt], afr[mt][kk], bb[nt]);
        }

        // ---- epilogue: acc-space max + certified gate ----
#pragma unroll
        for (int mt = 0; mt < 2; mt++)
#pragma unroll
            for (int h = 0; h < 2; h++) {
                int row  = 32 * wm + 16 * mt + g + 8 * h;
                int slot = mt * 2 + h;
                float av[8];
#pragma unroll
                for (int nt = 0; nt < 4; nt++) {
                    av[2 * nt]     = acc[mt][nt][2 * h];
                    av[2 * nt + 1] = acc[mt][nt][2 * h + 1];
                }
                float ml = av[0];
#pragma unroll
                for (int q = 1; q < 8; q++) ml = fmaxf(ml, av[q]);
                float mw = fmaxf(ml, __shfl_xor_sync(0xffffffffu, ml, 1));
                mw       = fmaxf(mw, __shfl_xor_sync(0xffffffffu, mw, 2));
                float ra   = unfkey(ROWA[row]);          // NaN-init ignored by fmaxf
                float best = fmaxf(bestApp[slot], fmaxf(ra, mw));
                float gate = best - MROW[row];

                if (__ballot_sync(0xffffffffu, ml > gate)) {
#pragma unroll
                    for (int q = 0; q < 8; q++) {
                        bool pr = av[q] > gate;
                        unsigned mask = __ballot_sync(0xffffffffu, pr);
                        if (mask) {
                            int pos = warpCnt + __popc(mask & ltmask);
                            if (pr) {
                                int jg = c * TILE_S + 32 * wn + 8 * (q >> 1) + 2 * tg + (q & 1);
                                if (pos < CAPW) {
                                    WCAND[pos] = (row << 10) | jg;
                                } else {   // rare overflow: inline exact rescore
                                    const float* e = cbk + (size_t)jg * DIM;
                                    float dot = 0.f;
#pragma unroll 8
                                    for (int d = 0; d < DIM; d++)
                                        dot = __fmaf_rn(A_EX[row * PAD + d], e[d], dot);
                                    float de = __fsub_rn(
                                        __fadd_rn(ZN[row], g_enorm[k * SENT + jg]),
                                        __fmul_rn(2.0f, dot));
                                    atomicMin(&ROWB[row],
                                              ((unsigned long long)fkey(de) << 32) | (unsigned)jg);
                                }
                            }
                            warpCnt += __popc(mask);
                        }
                    }
                }
                bestApp[slot] = fmaxf(bestApp[slot], mw);
                if (tg == 0) atomicMax(&ROWA[row], fkey(mw));
            }
    }
    if (lane == 0) WCNTS[warp] = warpCnt;
    __syncthreads();

    // ---- deferred exact rescore (R1 sequential-FMA rounding; (dist,idx) key) ----
#pragma unroll
    for (int w = 0; w < 8; w++) {
        int cw = WCNTS[w]; if (cw > CAPW) cw = CAPW;
        for (int ci = tid; ci < cw; ci += 256) {
            int cd  = CANDS[w * CAPW + ci];
            int row = cd >> 10, jg = cd & 1023;
            const float* e = cbk + (size_t)jg * DIM;
            float dot = 0.f;
#pragma unroll 8
            for (int d = 0; d < DIM; d++)
                dot = __fmaf_rn(A_EX[row * PAD + d], e[d], dot);
            float de = __fsub_rn(__fadd_rn(ZN[row], g_enorm[k * SENT + jg]),
                                 __fmul_rn(2.0f, dot));
            atomicMin(&ROWB[row], ((unsigned long long)fkey(de) << 32) | (unsigned)jg);
        }
    }
    __syncthreads();

    // ---- outputs: indices, z_q gather, loss partial ----
    if (tid < 128 && idx_off >= 0)
        out[(size_t)idx_off + (size_t)k * NPOS + tileBase + tid] = (float)(ROWB[tid] & 1023u);

    const int bestI = (int)(ROWB[zrow] & 1023u);
    const float* crow = cb + ((size_t)(k * SENT + bestI)) * DIM;
    const size_t obase = ((size_t)(b * 256 + k * DIM)) * HW_ + hw0 + zrow;
    double loc = 0.0;
#pragma unroll
    for (int i = 0; i < 32; i++) {
        int d = d0 + i;
        float val = __ldg(crow + d);
        float zv  = A_EX[zrow * PAD + d];
        out[obase + (size_t)d * HW_] = val;     // coalesced across zrow
        float diff = val - zv;
        loc += (double)diff * (double)diff;
    }
    __syncthreads();                            // CANDS no longer needed
    double* sred = (double*)(smc + OF_CAND);
    sred[tid] = loc;
    __syncthreads();
    for (int s = 128; s > 0; s >>= 1) {
        if (tid < s) sred[tid] += sred[tid + s];
        __syncthreads();
    }
    if (tid == 0) g_part[k * (NPOS / TILE_N) + blockIdx.x] = sred[0];
}

// ---------------------------------------------------------------------------
__global__ void finalize_kernel(float* __restrict__ out, int loss_off) {
    if (loss_off < 0) return;
    __shared__ double sred[256];
    double s = 0.0;
    for (int i = threadIdx.x; i < KCB * (NPOS / TILE_N); i += 256) s += g_part[i];
    sred[threadIdx.x] = s;
    __syncthreads();
    for (int st = 128; st > 0; st >>= 1) {
        if (threadIdx.x < st) sred[threadIdx.x] += sred[threadIdx.x + st];
        __syncthreads();
    }
    if (threadIdx.x == 0) out[loss_off] = (float)(1.25 * sred[0] / (double)ZQ_ELEMS);
}

// ---------------------------------------------------------------------------
extern "C" void kernel_launch(void* const* d_in, const int* in_sizes, int n_in,
                              void* d_out, int out_size) {
    const float* z  = (const float*)d_in[0];
    const float* cb = (const float*)d_in[1];
    if (n_in >= 2 && in_sizes[0] == KCB * SENT * DIM) {
        cb = (const float*)d_in[0];
        z  = (const float*)d_in[1];
    }
    float* out = (float*)d_out;

    int loss_off = -1, idx_off = -1;
    if (out_size == ZQ_ELEMS + 1 + KCB * NPOS) { loss_off = ZQ_ELEMS; idx_off = ZQ_ELEMS + 1; }
    else if (out_size == ZQ_ELEMS + KCB * NPOS) { idx_off = ZQ_ELEMS; }

    cudaFuncSetAttribute(vq_main_kernel, cudaFuncAttributeMaxDynamicSharedMemorySize, SMEM_TOTAL);

    enorm_kernel<<<KCB * SENT / 256, 256>>>(cb);

    dim3 ga(NPOS / TILE_N, KCB);
    vq_main_kernel<<<ga, 256, SMEM_TOTAL>>>(z, cb, out, idx_off);

    finalize_kernel<<<1, 256>>>(out, loss_off);
}